// round 15
// baseline (speedup 1.0000x reference)
#include <cuda_runtime.h>
#include <cuda_fp16.h>
#include <cstdint>

// ---------------------------------------------------------------------------
// MultiLevelFeatureSampler on GB300 (sm_103a via base-target sm_103 SASS)
//
// Per point: D[128x256] = P[128x83] @ W^T (+ bias); P = gather of 83 taps.
// Two-product fp16 scheme: A -> fp16, B -> fp16 split (bh, bl);
// D = ah*bh + ah*bl  (rel_err 2.06e-4, measured).
//
// R15: ROW-VECTORIZED GATHER.  Taps within a patch row are consecutive
// pixels; each of the 15 patch rows is fetched as 2-3 aligned 16B cp.async
// segments (4736 vs 10624 copies/point; ~2 L2 sectors/row vs 7).  Convert
// indexes raw via a per-tap offset table (exactly reproduces per-tap
// clamping).  MMA/epilogue = EXACT R11 structure (any restructuring there
// regressed in R12/R13).  Persistent CTAs (grid=148, 512 thr), resident B,
// fire-and-forget gather for p+1 during MMA of p, st.global.cs epilogue.
// ---------------------------------------------------------------------------

#define NSM   148
#define NPTS_TOTAL 2048
#define CCH   128
#define DTOT  83
#define GTOT  (CCH * DTOT)
#define STRD  104              // A row stride in fp16 (208 B)
#define NOUT  256
#define NTHR  512

#define H0 93
#define W0 305
#define H1 47
#define W1 153
#define H2 24
#define W2 77

#define NROW  15               // 7 + 5 + 3 patch rows
#define RAWCH 148              // floats per channel in raw: 7*12 + 5*8 + 3*8

// ---- smem layout (bytes) ----
#define OFF_ROWT    0                              // 15 * 16B {ptr, stride}
#define OFF_TAPD    256                            // 83 * 4B tap descriptors
#define OFF_BIAS    640                            // 256 * 4B -> ends 1664
#define OFF_A       1664                           // 128 x 208B = 26624
#define OFF_RAW     (OFF_A + CCH * STRD * 2)       // 28288, 128*148*4 = 75776
#define OFF_BH      (OFF_RAW + CCH * RAWCH * 4)    // 104064 (256 x 208B fp16)
#define OFF_BL      (OFF_BH + NOUT * STRD * 2)     // 157312
#define SMEM_TOTAL  (OFF_BL + NOUT * STRD * 2)     // 210560 (~205.6 KB)

// W split-fp16 scratch, [0]=hi, [1]=lo, row-major 256 x STRD (pads zeroed)
__device__ __align__(16) __half g_B[2][NOUT * STRD];

// ---------------------------------------------------------------------------
__device__ __forceinline__ uint32_t smem_u32(const void* p) {
    uint32_t a;
    asm("{ .reg .u64 t; cvta.to.shared.u64 t, %1; cvt.u32.u64 %0, t; }"
        : "=r"(a) : "l"(p));
    return a;
}

__device__ __forceinline__ void cp16(uint32_t dst, const void* src) {
    asm volatile("cp.async.cg.shared.global [%0], [%1], 16;"
                 :: "r"(dst), "l"(src) : "memory");
}

__device__ __forceinline__ void ldsm4(uint32_t* r, uint32_t addr) {
    asm volatile("ldmatrix.sync.aligned.m8n8.x4.shared.b16 {%0,%1,%2,%3}, [%4];"
                 : "=r"(r[0]), "=r"(r[1]), "=r"(r[2]), "=r"(r[3]) : "r"(addr));
}

__device__ __forceinline__ void hmma(float* c, const uint32_t* a, const uint32_t* b) {
    asm volatile(
        "mma.sync.aligned.m16n8k16.row.col.f32.f16.f16.f32 "
        "{%0,%1,%2,%3}, {%4,%5,%6,%7}, {%8,%9}, {%0,%1,%2,%3};"
        : "+f"(c[0]), "+f"(c[1]), "+f"(c[2]), "+f"(c[3])
        : "r"(a[0]), "r"(a[1]), "r"(a[2]), "r"(a[3]), "r"(b[0]), "r"(b[1]));
}

__device__ __forceinline__ void stcs2(float* p, float x, float y) {
    asm volatile("st.global.cs.v2.f32 [%0], {%1, %2};"
                 :: "l"(p), "f"(x), "f"(y) : "memory");
}

// slot start (floats, within a channel's raw region) for patch row 0..14
__device__ __forceinline__ int row_slot(int row) {
    return (row < 7) ? row * 12
         : (row < 12) ? 84 + (row - 7) * 8
                      : 124 + (row - 12) * 8;
}

// Per-tap metadata for point pn (d < 83).  Writes:
//  - tap descriptor: foff(16b) | b0(2b at 16) | s3(2b at 18)
//      foff = row_slot + (ox_d - ox_row0);  shift_c = (b0 + c*s3) & 3
//  - row entry (k==0 tap): {base ptr (row start, clamped), stride}
__device__ __forceinline__ void compute_taps(char* smem, int d, int pn,
                                             const float* __restrict__ points,
                                             const float* __restrict__ feat0,
                                             const float* __restrict__ feat1,
                                             const float* __restrict__ feat2) {
    const float* f; int H, Wd, ks, dd, row;
    if (d < 49)      { f = feat0; H = H0; Wd = W0; ks = 7; dd = d;      row = dd / 7; }
    else if (d < 74) { f = feat1; H = H1; Wd = W1; ks = 5; dd = d - 49; row = 7 + dd / 5; }
    else             { f = feat2; H = H2; Wd = W2; ks = 3; dd = d - 74; row = 12 + dd / 3; }
    int half = ks >> 1;
    int jj = dd / ks - half;
    int kk = dd % ks - half;
    int bi = pn >> 9;
    float px = points[pn * 2 + 0];
    float py = points[pn * 2 + 1];
    float x = fminf(fmaxf(px * (float)(Wd - 1), 0.f), (float)(Wd - 1));
    float y = fminf(fmaxf(py * (float)(H  - 1), 0.f), (float)(H  - 1));
    int oy  = (int)floorf(fminf(fmaxf(y + (float)jj, 0.f), (float)(H  - 1)));
    int ox  = (int)floorf(fminf(fmaxf(x + (float)kk, 0.f), (float)(Wd - 1)));
    int ox0 = (int)floorf(fminf(fmaxf(x - (float)half, 0.f), (float)(Wd - 1)));
    const float* bp = f + (size_t)bi * CCH * H * Wd + oy * Wd + ox0;
    uint32_t b0 = ((uint32_t)(uintptr_t)bp >> 2) & 3;
    uint32_t s3 = (uint32_t)(H * Wd) & 3;
    uint32_t w = (uint32_t)(row_slot(row) + (ox - ox0)) | (b0 << 16) | (s3 << 18);
    *(uint32_t*)(smem + OFF_TAPD + d * 4) = w;
    if (kk == -half) {
        char* ent = smem + OFF_ROWT + row * 16;
        *(const float**)(ent) = bp;
        *(int*)(ent + 8) = H * Wd;
    }
}

// Row-vectorized gather: 128 channels x 15 rows; 2-3 aligned 16B cp.async
// segments per (c,row) into the raw slot.  Fire-and-forget.
__device__ __forceinline__ void gather_rows(char* smem, uint32_t raw, int tid) {
    #pragma unroll
    for (int i = 0; i < 4; ++i) {
        int idx = tid + NTHR * i;
        if (idx < CCH * NROW) {
            int c = idx / NROW;
            int row = idx - c * NROW;
            uint4 te = *(const uint4*)(smem + OFF_ROWT + row * 16);
            const char* bp;
            asm("mov.b64 %0, {%1, %2};" : "=l"(bp) : "r"(te.x), "r"(te.y));
            int st = (int)te.z;                       // stride in floats
            const char* fp = bp + (size_t)c * st * 4;
            const char* ap = (const char*)((uintptr_t)fp & ~(uintptr_t)15);
            uint32_t dst = raw + (uint32_t)(c * (RAWCH * 4) + row_slot(row) * 4);
            cp16(dst, ap);
            cp16(dst + 16, ap + 16);
            if (row < 7) cp16(dst + 32, ap + 32);     // 7-wide rows need 48B
        }
    }
}

// Convert raw -> fp16 A using per-tap descriptors (exact per-tap clamping).
__device__ __forceinline__ void convert_raw(char* smem, int tid) {
    const float* raw = (const float*)(smem + OFF_RAW);
    char* ah = smem + OFF_A;
    int c = tid / DTOT;
    int d = tid - c * DTOT;
    #pragma unroll 7
    for (int i = 0; i < 21; ++i) {
        int e = tid + NTHR * i;
        if (e < GTOT) {
            uint32_t w = *(const uint32_t*)(smem + OFF_TAPD + d * 4);
            int foff = (int)(w & 0xffff);
            int shift = (int)(((w >> 16) + (uint32_t)c * (w >> 18)) & 3);
            float v = raw[c * RAWCH + foff + shift];
            *(__half*)(ah + c * 208 + d * 2) = __float2half(v);
        }
        c += 6; d += 14;                // 512 = 6*83 + 14
        if (d >= DTOT) { d -= DTOT; c += 1; }
    }
}

// ---------------------------------------------------------------------------
// Prologue: W (256x83 fp32) -> g_B hi/lo fp16, row stride STRD, pads zeroed.
__global__ void prep_B_kernel(const float* __restrict__ Wg) {
    int idx = blockIdx.x * 256 + threadIdx.x;
    if (idx >= NOUT * STRD) return;
    int row = idx / STRD;
    int col = idx - row * STRD;
    float v = (col < DTOT) ? Wg[row * DTOT + col] : 0.f;
    __half hi = __float2half(v);
    __half lo = __float2half(v - __half2float(hi));
    g_B[0][idx] = hi;
    g_B[1][idx] = lo;
}

// ---------------------------------------------------------------------------
__global__ void __launch_bounds__(NTHR, 1)
mlfs_kernel(const float* __restrict__ points,
            const float* __restrict__ feat0,
            const float* __restrict__ feat1,
            const float* __restrict__ feat2,
            const float* __restrict__ biasg,
            float* __restrict__ out) {
    extern __shared__ char smem[];
    const uint32_t smem_base = smem_u32(smem);
    const int tid = threadIdx.x;
    const int wid = tid >> 5;
    const int lane = tid & 31;
    const int r = blockIdx.x;

    // ---- setup: B resident copy (async), bias, A-pad zero ----
    {
        const char* src = (const char*)g_B;
        uint32_t dst = smem_base + OFF_BH;
        const int n16 = (2 * NOUT * STRD * 2) / 16;   // 6656
        #pragma unroll 2
        for (int i = tid; i < n16; i += NTHR)
            cp16(dst + i * 16, src + (size_t)i * 16);
    }
    if (tid < 64)
        ((float4*)(smem + OFF_BIAS))[tid] = ((const float4*)biasg)[tid];

    // zero A pad bytes 160..207 of every row (cols 80..103; convert rewrites
    // 160..165 each point): 128 rows, tid<128
    if (tid < 128) {
        float4 z = make_float4(0.f, 0.f, 0.f, 0.f);
        char* base = smem + OFF_A + tid * 208 + 160;
        ((float4*)base)[0] = z; ((float4*)base)[1] = z; ((float4*)base)[2] = z;
    }

    // taps for first point, then issue its gather
    if (tid < DTOT)
        compute_taps(smem, tid, r, points, feat0, feat1, feat2);
    __syncthreads();
    gather_rows(smem, smem_base + OFF_RAW, tid);
    asm volatile("cp.async.commit_group;" ::: "memory");

    // ---- persistent loop ----
    const int wm = wid >> 2;            // 0..3 (M, 32-row tiles)
    const int wn = wid & 3;             // 0..3 (N, 32-col tiles within half)
    const uint32_t lrow = lane & 15;
    const uint32_t kof2 = ((lane >> 4) << 3) * 2;
    const float* bs = (const float*)(smem + OFF_BIAS);

    for (int p = r; p < NPTS_TOTAL; p += NSM) {
        const int pn = p + NSM;
        const bool hasnext = (pn < NPTS_TOTAL);

        asm volatile("cp.async.wait_group 0;" ::: "memory");
        __syncthreads();                 // raw ready; MMA of p-1 done with A

        convert_raw(smem, tid);          // raw -> fp16 A  (raw + tables free)
        __syncthreads();                 // A ready before tables overwritten
        if (tid < DTOT && hasnext)
            compute_taps(smem, tid, pn, points, feat0, feat1, feat2);
        __syncthreads();                 // tables ready; raw free

        if (hasnext) {
            gather_rows(smem, smem_base + OFF_RAW, tid);    // fire and forget
            asm volatile("cp.async.commit_group;" ::: "memory");
        }

        // ---- two-product MMA + epilogue (EXACT R11 structure) ----
        float* outp = out + (size_t)p * (CCH * NOUT);
        #pragma unroll
        for (int hh = 0; hh < 2; ++hh) {
            float acc[2][4][4];
            #pragma unroll
            for (int mt = 0; mt < 2; ++mt)
                #pragma unroll
                for (int nt = 0; nt < 4; ++nt)
                    #pragma unroll
                    for (int q = 0; q < 4; ++q) acc[mt][nt][q] = 0.f;

            const uint32_t aAddr0 = smem_base + OFF_A
                                  + (wm * 32 + lrow) * 208 + kof2;
            const uint32_t bAddrH = smem_base + OFF_BH
                                  + (hh * 128 + wn * 32 + lrow) * 208 + kof2;
            #pragma unroll
            for (int ks = 0; ks < 6; ++ks) {
                uint32_t a[2][4], bh[4][2], bl[4][2], t[4];
                #pragma unroll
                for (int mt = 0; mt < 2; ++mt)
                    ldsm4(a[mt], aAddr0 + mt * 16 * 208 + ks * 32);
                #pragma unroll
                for (int np = 0; np < 2; ++np) {
                    ldsm4(t, bAddrH + np * 16 * 208 + ks * 32);
                    bh[2 * np + 0][0] = t[0]; bh[2 * np + 1][0] = t[1];
                    bh[2 * np + 0][1] = t[2]; bh[2 * np + 1][1] = t[3];
                    ldsm4(t, bAddrH + (OFF_BL - OFF_BH) + np * 16 * 208 + ks * 32);
                    bl[2 * np + 0][0] = t[0]; bl[2 * np + 1][0] = t[1];
                    bl[2 * np + 0][1] = t[2]; bl[2 * np + 1][1] = t[3];
                }
                #pragma unroll
                for (int mt = 0; mt < 2; ++mt)
                    #pragma unroll
                    for (int nt = 0; nt < 4; ++nt) {
                        hmma(acc[mt][nt], a[mt], bh[nt]);
                        hmma(acc[mt][nt], a[mt], bl[nt]);
                    }
            }

            // epilogue for this 128-col half (streaming stores)
            const int r0 = wm * 32 + (lane >> 2);
            const int c0 = wn * 32 + 2 * (lane & 3);
            float2 bv[4];
            #pragma unroll
            for (int nt = 0; nt < 4; ++nt)
                bv[nt] = *(const float2*)(bs + hh * 128 + c0 + nt * 8);
            float* oph = outp + hh * 128;
            #pragma unroll
            for (int mt = 0; mt < 2; ++mt) {
                const int row = r0 + mt * 16;
                #pragma unroll
                for (int nt = 0; nt < 4; ++nt) {
                    const int col = c0 + nt * 8;
                    stcs2(oph + (size_t)row * NOUT + col,
                          acc[mt][nt][0] + bv[nt].x, acc[mt][nt][1] + bv[nt].y);
                    stcs2(oph + (size_t)(row + 8) * NOUT + col,
                          acc[mt][nt][2] + bv[nt].x, acc[mt][nt][3] + bv[nt].y);
                }
            }
        }
    }
}

// ---------------------------------------------------------------------------
extern "C" void kernel_launch(void* const* d_in, const int* in_sizes, int n_in,
                              void* d_out, int out_size) {
    const float* points = (const float*)d_in[0];
    const float* feat0  = (const float*)d_in[1];
    const float* feat1  = (const float*)d_in[2];
    const float* feat2  = (const float*)d_in[3];
    const float* Wg     = (const float*)d_in[4];
    const float* biasg  = (const float*)d_in[5];
    float* out = (float*)d_out;

    prep_B_kernel<<<(NOUT * STRD + 255) / 256, 256>>>(Wg);

    cudaFuncSetAttribute(mlfs_kernel,
                         cudaFuncAttributeMaxDynamicSharedMemorySize, SMEM_TOTAL);
    mlfs_kernel<<<NSM, NTHR, SMEM_TOTAL>>>(points, feat0, feat1, feat2,
                                           biasg, out);
}